// round 8
// baseline (speedup 1.0000x reference)
#include <cuda_runtime.h>
#include <cuda_bf16.h>

#define BLK 256
#define WPC 8
#define MAX_PARTIALS 8192

#define LOG2E 1.44269504088896340736f
#define LN2   0.69314718055994530942f

typedef unsigned long long u64;

__device__ float g_partials[MAX_PARTIALS];
__device__ int   g_done = 0;

__device__ __forceinline__ float ex2f(float x) {
    float r; asm("ex2.approx.ftz.f32 %0, %1;" : "=f"(r) : "f"(x)); return r;
}
__device__ __forceinline__ float lg2f(float x) {
    float r; asm("lg2.approx.ftz.f32 %0, %1;" : "=f"(r) : "f"(x)); return r;
}

// ---- packed f32x2 helpers (sm_103a) ----
__device__ __forceinline__ u64 pack2(float lo, float hi) {
    u64 r; asm("mov.b64 %0, {%1, %2};" : "=l"(r) : "f"(lo), "f"(hi)); return r;
}
__device__ __forceinline__ void unpack2(u64 v, float& lo, float& hi) {
    asm("mov.b64 {%0, %1}, %2;" : "=f"(lo), "=f"(hi) : "l"(v));
}
__device__ __forceinline__ u64 mul2(u64 a, u64 b) {
    u64 r; asm("mul.rn.f32x2 %0, %1, %2;" : "=l"(r) : "l"(a), "l"(b)); return r;
}
__device__ __forceinline__ u64 add2(u64 a, u64 b) {
    u64 r; asm("add.rn.f32x2 %0, %1, %2;" : "=l"(r) : "l"(a), "l"(b)); return r;
}
__device__ __forceinline__ u64 fma2(u64 a, u64 b, u64 c) {
    u64 r; asm("fma.rn.f32x2 %0, %1, %2, %3;" : "=l"(r) : "l"(a), "l"(b), "l"(c)); return r;
}

__inline__ __device__ float warp_sum(float v) {
    #pragma unroll
    for (int o = 16; o > 0; o >>= 1)
        v += __shfl_xor_sync(0xFFFFFFFFu, v, o);
    return v;
}

// One warp per row. Per element: e = 2^(v*log2e) (= exp v),
// l2 = log2(1 + e*K), K = exp(-extra). Row value = (Σ e*l2)/(Σ e);
// final loss = (Σ_rows rowval) * ln2 / B.
__global__ __launch_bounds__(BLK) void loss_kernel(
    const float* __restrict__ in, int C, int B, float* __restrict__ out)
{
    const int t    = threadIdx.x;
    const int lane = t & 31;
    const int wid  = t >> 5;
    const int row  = blockIdx.x * WPC + wid;

    __shared__ float sh_row[WPC];

    float se_s = 0.0f, sl_s = 0.0f;          // scalar (head/tail) accumulators
    u64 acc_se = 0, acc_sl = 0;              // packed f32x2 accumulators (0,0)

    if (row < B) {
        const size_t S = (size_t)row * (size_t)(C + 1);   // row start (floats)
        const float extra = __ldg(in + S + C);
        const float Kf = ex2f(-extra * LOG2E);            // exp(-extra)

        const u64 LOG2E2 = pack2(LOG2E, LOG2E);
        const u64 K2     = pack2(Kf, Kf);
        const u64 ONE2   = pack2(1.0f, 1.0f);

        const size_t A = (S + 3) & ~(size_t)3;            // 16B-aligned start
        const int head = (int)(A - S);                    // 0..3 scalar head elems

        if (lane < head) {
            const float v = __ldg(in + S + lane);
            const float e = ex2f(v * LOG2E);
            const float l2 = lg2f(fmaf(e, Kf, 1.0f));
            se_s += e;
            sl_s = fmaf(e, l2, sl_s);
        }

        const float4* __restrict__ fp4 = (const float4*)(in + A);
        const int body = (int)((size_t)(S + C) - A);      // floats in aligned body+tail
        const int n4   = body >> 2;
        const int tail = body & 3;
        const int nfull = n4 >> 5;                        // full 32-wide f4 iterations

        #pragma unroll 4
        for (int k = 0; k < nfull; k++) {
            const float4 q = __ldg(fp4 + (k << 5) + lane);
            // scale by log2e (packed)
            const u64 w01 = mul2(pack2(q.x, q.y), LOG2E2);
            const u64 w23 = mul2(pack2(q.z, q.w), LOG2E2);
            float w0, w1, w2, w3;
            unpack2(w01, w0, w1); unpack2(w23, w2, w3);
            const float e0 = ex2f(w0), e1 = ex2f(w1);
            const float e2 = ex2f(w2), e3 = ex2f(w3);
            const u64 e01 = pack2(e0, e1);
            const u64 e23 = pack2(e2, e3);
            // u = e*K + 1 (packed)
            const u64 u01 = fma2(e01, K2, ONE2);
            const u64 u23 = fma2(e23, K2, ONE2);
            float u0, u1, u2, u3;
            unpack2(u01, u0, u1); unpack2(u23, u2, u3);
            const float l0 = lg2f(u0), l1 = lg2f(u1);
            const float l2 = lg2f(u2), l3 = lg2f(u3);
            // accumulate (packed)
            acc_se = add2(acc_se, e01);
            acc_se = add2(acc_se, e23);
            acc_sl = fma2(e01, pack2(l0, l1), acc_sl);
            acc_sl = fma2(e23, pack2(l2, l3), acc_sl);
        }
        {   // remainder float4s
            const int i = (nfull << 5) + lane;
            if (i < n4) {
                const float4 q = __ldg(fp4 + i);
                const u64 w01 = mul2(pack2(q.x, q.y), LOG2E2);
                const u64 w23 = mul2(pack2(q.z, q.w), LOG2E2);
                float w0, w1, w2, w3;
                unpack2(w01, w0, w1); unpack2(w23, w2, w3);
                const float e0 = ex2f(w0), e1 = ex2f(w1);
                const float e2 = ex2f(w2), e3 = ex2f(w3);
                const u64 e01 = pack2(e0, e1);
                const u64 e23 = pack2(e2, e3);
                const u64 u01 = fma2(e01, K2, ONE2);
                const u64 u23 = fma2(e23, K2, ONE2);
                float u0, u1, u2, u3;
                unpack2(u01, u0, u1); unpack2(u23, u2, u3);
                const float l0 = lg2f(u0), l1 = lg2f(u1);
                const float l2 = lg2f(u2), l3 = lg2f(u3);
                acc_se = add2(acc_se, e01);
                acc_se = add2(acc_se, e23);
                acc_sl = fma2(e01, pack2(l0, l1), acc_sl);
                acc_sl = fma2(e23, pack2(l2, l3), acc_sl);
            }
        }
        if (lane < tail) {   // scalar tail
            const float v = __ldg(in + S + C - tail + lane);
            const float e = ex2f(v * LOG2E);
            const float l2 = lg2f(fmaf(e, Kf, 1.0f));
            se_s += e;
            sl_s = fmaf(e, l2, sl_s);
        }
    }

    // fold packed accumulators into scalars
    {
        float a, b, c, d;
        unpack2(acc_se, a, b);
        unpack2(acc_sl, c, d);
        se_s += a + b;
        sl_s += c + d;
    }

    float se = warp_sum(se_s);
    float sl = warp_sum(sl_s);
    if (lane == 0)
        sh_row[wid] = (row < B) ? (sl / se) : 0.0f;
    __syncthreads();

    __shared__ bool is_last;
    if (t == 0) {
        float part = 0.0f;
        #pragma unroll
        for (int i = 0; i < WPC; i++) part += sh_row[i];
        g_partials[blockIdx.x] = part;
        __threadfence();
        is_last = (atomicAdd(&g_done, 1) == (int)gridDim.x - 1);
    }
    __syncthreads();

    if (is_last) {
        const int nP = gridDim.x;
        float s = 0.0f;
        for (int i = t; i < nP; i += BLK) s += g_partials[i];
        s = warp_sum(s);
        __shared__ float sh_fin[BLK / 32];
        if (lane == 0) sh_fin[t >> 5] = s;
        __syncthreads();
        if (t == 0) {
            float tot = 0.0f;
            #pragma unroll
            for (int i = 0; i < BLK / 32; i++) tot += sh_fin[i];
            out[0] = tot * (LN2 / (float)B);
            g_done = 0;   // reset for next graph replay
        }
    }
}

extern "C" void kernel_launch(void* const* d_in, const int* in_sizes, int n_in,
                              void* d_out, int out_size)
{
    const float* input = (const float*)d_in[0];
    const int B = in_sizes[1];             // target has B elements
    const int C = in_sizes[0] / B - 1;     // logits per row (row stride C+1)
    float* out = (float*)d_out;

    const int grid = (B + WPC - 1) / WPC;  // 8192 for B=65536
    loss_kernel<<<grid, BLK>>>(input, C, B, out);
}

// round 9
// speedup vs baseline: 1.2232x; 1.2232x over previous
#include <cuda_runtime.h>
#include <cuda_bf16.h>

#define BLK 256
#define WPC 8
#define GRID_CTAS 1184            /* 148 SMs * 8 CTAs */
#define MAX_PARTIALS 8192

#define LOG2E 1.44269504088896340736f
#define LN2   0.69314718055994530942f

__device__ float g_partials[MAX_PARTIALS];
__device__ int   g_done = 0;

__device__ __forceinline__ float ex2f(float x) {
    float r; asm("ex2.approx.ftz.f32 %0, %1;" : "=f"(r) : "f"(x)); return r;
}
__device__ __forceinline__ float lg2f(float x) {
    float r; asm("lg2.approx.ftz.f32 %0, %1;" : "=f"(r) : "f"(x)); return r;
}

__inline__ __device__ float warp_sum(float v) {
    #pragma unroll
    for (int o = 16; o > 0; o >>= 1)
        v += __shfl_xor_sync(0xFFFFFFFFu, v, o);
    return v;
}

// Persistent kernel: each warp owns rows {warp_gid, warp_gid+W, ...}.
// Per element: e = 2^(v*log2e), l2 = log2(1 + e*K), K = exp(-extra).
// Row value = (Σ e*l2)/(Σ e); final loss = (Σ rows) * ln2 / B.
__global__ __launch_bounds__(BLK) void loss_kernel(
    const float* __restrict__ in, int C, int B, float* __restrict__ out)
{
    const int t    = threadIdx.x;
    const int lane = t & 31;
    const int wid  = t >> 5;
    const int warp_gid = blockIdx.x * WPC + wid;
    const int nwarps   = gridDim.x * WPC;

    __shared__ float sh_row[WPC];

    float rowacc = 0.0f;   // sum over this warp's rows of sl/se (uniform per warp)

    for (int row = warp_gid; row < B; row += nwarps) {
        const size_t S = (size_t)row * (size_t)(C + 1);   // row start (floats)
        const float extra = __ldg(in + S + C);
        const float K = ex2f(-extra * LOG2E);             // exp(-extra)

        const size_t A = (S + 3) & ~(size_t)3;            // 16B-aligned start
        const int head = (int)(A - S);                    // 0..3 scalar head elems

        float se = 0.0f, sl = 0.0f;

        if (lane < head) {
            const float v = __ldg(in + S + lane);
            const float e = ex2f(v * LOG2E);
            const float l2 = lg2f(fmaf(e, K, 1.0f));
            se += e;
            sl = fmaf(e, l2, sl);
        }

        const float4* __restrict__ fp4 = (const float4*)(in + A);
        const int body = (int)((size_t)(S + C) - A);      // floats in aligned body+tail
        const int n4   = body >> 2;
        const int tail = body & 3;
        const int nfull = n4 >> 5;                        // full 32-wide f4 iterations

        #pragma unroll 4
        for (int k = 0; k < nfull; k++) {
            const float4 q = __ldg(fp4 + (k << 5) + lane);
            const float e0 = ex2f(q.x * LOG2E);
            const float e1 = ex2f(q.y * LOG2E);
            const float e2 = ex2f(q.z * LOG2E);
            const float e3 = ex2f(q.w * LOG2E);
            const float l0 = lg2f(fmaf(e0, K, 1.0f));
            const float l1 = lg2f(fmaf(e1, K, 1.0f));
            const float l2 = lg2f(fmaf(e2, K, 1.0f));
            const float l3 = lg2f(fmaf(e3, K, 1.0f));
            se += (e0 + e1) + (e2 + e3);
            sl = fmaf(e0, l0, sl);
            sl = fmaf(e1, l1, sl);
            sl = fmaf(e2, l2, sl);
            sl = fmaf(e3, l3, sl);
        }
        {   // remainder float4s
            const int i = (nfull << 5) + lane;
            if (i < n4) {
                const float4 q = __ldg(fp4 + i);
                const float e0 = ex2f(q.x * LOG2E);
                const float e1 = ex2f(q.y * LOG2E);
                const float e2 = ex2f(q.z * LOG2E);
                const float e3 = ex2f(q.w * LOG2E);
                const float l0 = lg2f(fmaf(e0, K, 1.0f));
                const float l1 = lg2f(fmaf(e1, K, 1.0f));
                const float l2 = lg2f(fmaf(e2, K, 1.0f));
                const float l3 = lg2f(fmaf(e3, K, 1.0f));
                se += (e0 + e1) + (e2 + e3);
                sl = fmaf(e0, l0, sl);
                sl = fmaf(e1, l1, sl);
                sl = fmaf(e2, l2, sl);
                sl = fmaf(e3, l3, sl);
            }
        }
        if (lane < tail) {   // scalar tail
            const float v = __ldg(in + S + C - tail + lane);
            const float e = ex2f(v * LOG2E);
            const float l2 = lg2f(fmaf(e, K, 1.0f));
            se += e;
            sl = fmaf(e, l2, sl);
        }

        se = warp_sum(se);
        sl = warp_sum(sl);
        rowacc += sl / se;
    }

    if (lane == 0) sh_row[wid] = rowacc;
    __syncthreads();

    __shared__ bool is_last;
    if (t == 0) {
        float part = 0.0f;
        #pragma unroll
        for (int i = 0; i < WPC; i++) part += sh_row[i];
        g_partials[blockIdx.x] = part;
        __threadfence();
        is_last = (atomicAdd(&g_done, 1) == (int)gridDim.x - 1);
    }
    __syncthreads();

    if (is_last) {
        const int nP = gridDim.x;
        float s = 0.0f;
        for (int i = t; i < nP; i += BLK) s += g_partials[i];
        s = warp_sum(s);
        __shared__ float sh_fin[BLK / 32];
        if (lane == 0) sh_fin[t >> 5] = s;
        __syncthreads();
        if (t == 0) {
            float tot = 0.0f;
            #pragma unroll
            for (int i = 0; i < BLK / 32; i++) tot += sh_fin[i];
            out[0] = tot * (LN2 / (float)B);
            g_done = 0;   // reset for next graph replay
        }
    }
}

extern "C" void kernel_launch(void* const* d_in, const int* in_sizes, int n_in,
                              void* d_out, int out_size)
{
    const float* input = (const float*)d_in[0];
    const int B = in_sizes[1];             // target has B elements
    const int C = in_sizes[0] / B - 1;     // logits per row (row stride C+1)
    float* out = (float*)d_out;

    loss_kernel<<<GRID_CTAS, BLK>>>(input, C, B, out);
}